// round 3
// baseline (speedup 1.0000x reference)
#include <cuda_runtime.h>
#include <cuda_bf16.h>

// 3x3 median filter, zero padding, exact median of 9.
// x: (32, 3, 512, 512) fp32 -> 96 images of 512x512.
//
// Thread = 4 columns x 2 output rows (8 px). Lanes are contiguous in x
// (16B stride) so every LDG.128/STG.128 is 4 L1 wavefronts (minimal).
// Edge columns come from warp shuffles instead of scattered scalar loads.
// The two output rows share sort2(b,c) per column: 8 ops/col for both
// vertical triples. ~16 FMNMX/pixel total.

#define W 512
#define H 512
#define NIMG 96

__device__ __forceinline__ float med3(float a, float b, float c) {
    return fmaxf(fminf(a, b), fminf(fmaxf(a, b), c));
}

// Combine one output row: inputs lo[6], mi[6], hi[6] (sorted column triples),
// produce 4 window medians with pair-sharing. Writes o[4].
__device__ __forceinline__ void combine_row(const float* lo, const float* mi,
                                            const float* hi, float* o) {
    float wl[4], wh[4], wm[4];
    #pragma unroll
    for (int t = 0; t < 2; t++) {
        const int i = 2 * t + 1;
        const float A = fmaxf(lo[i], lo[i + 1]);
        wl[2 * t]     = fmaxf(A, lo[2 * t]);
        wl[2 * t + 1] = fmaxf(A, lo[2 * t + 3]);
        const float B = fminf(hi[i], hi[i + 1]);
        wh[2 * t]     = fminf(B, hi[2 * t]);
        wh[2 * t + 1] = fminf(B, hi[2 * t + 3]);
        const float mn = fminf(mi[i], mi[i + 1]);
        const float mx = fmaxf(mi[i], mi[i + 1]);
        wm[2 * t]     = fmaxf(mn, fminf(mx, mi[2 * t]));
        wm[2 * t + 1] = fminf(mx, fmaxf(mn, mi[2 * t + 3]));
    }
    #pragma unroll
    for (int j = 0; j < 4; j++)
        o[j] = med3(wl[j], wm[j], wh[j]);
}

__global__ void __launch_bounds__(256)
median3x3_kernel(const float* __restrict__ x, float* __restrict__ out) {
    const int tid  = blockIdx.x * blockDim.x + threadIdx.x;
    const int lane = threadIdx.x & 31;
    const int cb   = (tid & 127) << 2;      // column base (0..508), 128 thr/row-pair
    const int rp   = tid >> 7;              // row-pair id
    const int y0   = (rp & 255) << 1;       // even output row 0..510
    const float* img = x + ((size_t)(rp >> 8)) * (H * W);

    // Load 4 input rows (y0-1 .. y0+2), 6 columns each (cb-1 .. cb+4).
    float cols[4][6];
    #pragma unroll
    for (int dy = 0; dy < 4; dy++) {
        const int yy = y0 - 1 + dy;         // warp-uniform
        float* c = cols[dy];
        if (yy >= 0 && yy < H) {
            const float* rowp = img + yy * W;
            const float4 v = *reinterpret_cast<const float4*>(rowp + cb);
            float l = __shfl_up_sync(0xffffffffu, v.w, 1);
            float r = __shfl_down_sync(0xffffffffu, v.x, 1);
            if (lane == 0)  l = (cb > 0)     ? __ldg(rowp + cb - 1) : 0.0f;
            if (lane == 31) r = (cb + 4 < W) ? __ldg(rowp + cb + 4) : 0.0f;
            c[0] = l; c[1] = v.x; c[2] = v.y; c[3] = v.z; c[4] = v.w; c[5] = r;
        } else {
            #pragma unroll
            for (int i = 0; i < 6; i++) c[i] = 0.0f;
        }
    }

    // Shared middle sort2(b,c) per column, then insert a (row y0) / d (row y0+1).
    float mn[6], mx[6];
    #pragma unroll
    for (int i = 0; i < 6; i++) {
        mn[i] = fminf(cols[1][i], cols[2][i]);
        mx[i] = fmaxf(cols[1][i], cols[2][i]);
    }

    float lo[6], mi[6], hi[6], o[4];

    // Output row y0: triple (a, b, c) = (cols[0], mn, mx)
    #pragma unroll
    for (int i = 0; i < 6; i++) {
        const float a = cols[0][i];
        lo[i] = fminf(a, mn[i]);
        hi[i] = fmaxf(a, mx[i]);
        mi[i] = fmaxf(mn[i], fminf(a, mx[i]));
    }
    combine_row(lo, mi, hi, o);
    {
        float4 res; res.x = o[0]; res.y = o[1]; res.z = o[2]; res.w = o[3];
        *reinterpret_cast<float4*>(out + ((size_t)rp * 2 * W) + cb) = res;
    }

    // Output row y0+1: triple (b, c, d) = (mn, mx, cols[3])
    #pragma unroll
    for (int i = 0; i < 6; i++) {
        const float d = cols[3][i];
        lo[i] = fminf(d, mn[i]);
        hi[i] = fmaxf(d, mx[i]);
        mi[i] = fmaxf(mn[i], fminf(d, mx[i]));
    }
    combine_row(lo, mi, hi, o);
    {
        float4 res; res.x = o[0]; res.y = o[1]; res.z = o[2]; res.w = o[3];
        *reinterpret_cast<float4*>(out + ((size_t)(rp * 2 + 1) * W) + cb) = res;
    }
}

extern "C" void kernel_launch(void* const* d_in, const int* in_sizes, int n_in,
                              void* d_out, int out_size) {
    const float* x = (const float*)d_in[0];
    float* out = (float*)d_out;

    const int total_threads = (NIMG * H * W) / 8;   // 3,145,728
    const int block = 256;
    const int grid = total_threads / block;          // 12288
    median3x3_kernel<<<grid, block>>>(x, out);
}

// round 4
// speedup vs baseline: 1.1894x; 1.1894x over previous
#include <cuda_runtime.h>
#include <cuda_bf16.h>

// 3x3 median filter, zero padding, exact median of 9.
// x: (32, 3, 512, 512) fp32 -> 96 images of 512x512.
//
// Thread = 4 columns x 2 output rows (8 px), lanes contiguous in x (16B
// stride) -> minimal L1 wavefronts for the float4 loads/stores.
// ALL loads are unconditional (clamped addresses); zero-padding is applied
// by multiplying with 0/1 masks on the otherwise-idle FMA pipe. This keeps
// the 12 loads per thread front-batched (high MLP).
// The two output rows share sort2(midrows) per column. ~17.5 FMNMX/px.

#define W 512
#define H 512
#define NIMG 96

__device__ __forceinline__ float med3(float a, float b, float c) {
    return fmaxf(fminf(a, b), fminf(fmaxf(a, b), c));
}

// Combine one output row from sorted column triples lo/mi/hi[6] -> o[4].
__device__ __forceinline__ void combine_row(const float* lo, const float* mi,
                                            const float* hi, float* o) {
    float wl[4], wh[4], wm[4];
    #pragma unroll
    for (int t = 0; t < 2; t++) {
        const int i = 2 * t + 1;
        const float A = fmaxf(lo[i], lo[i + 1]);
        wl[2 * t]     = fmaxf(A, lo[2 * t]);
        wl[2 * t + 1] = fmaxf(A, lo[2 * t + 3]);
        const float B = fminf(hi[i], hi[i + 1]);
        wh[2 * t]     = fminf(B, hi[2 * t]);
        wh[2 * t + 1] = fminf(B, hi[2 * t + 3]);
        const float mn = fminf(mi[i], mi[i + 1]);
        const float mx = fmaxf(mi[i], mi[i + 1]);
        wm[2 * t]     = fmaxf(mn, fminf(mx, mi[2 * t]));
        wm[2 * t + 1] = fminf(mx, fmaxf(mn, mi[2 * t + 3]));
    }
    #pragma unroll
    for (int j = 0; j < 4; j++)
        o[j] = med3(wl[j], wm[j], wh[j]);
}

__global__ void __launch_bounds__(256)
median3x3_kernel(const float* __restrict__ x, float* __restrict__ out) {
    const int tid = blockIdx.x * blockDim.x + threadIdx.x;
    const int cb  = (tid & 127) << 2;        // column base (0..508)
    const int rp  = tid >> 7;                // row-pair id
    const int y0  = (rp & 255) << 1;         // even output row 0..510
    const float* img = x + ((size_t)(rp >> 8)) * (H * W);

    // Clamped row pointers (always valid to load).
    const int yt = (y0 == 0)       ? 0       : y0 - 1;   // top    (row y0-1)
    const int yb = (y0 == H - 2)   ? H - 1   : y0 + 2;   // bottom (row y0+2)
    const float* rt = img + yt * W;
    const float* r1p = img + y0 * W;
    const float* r2p = img + (y0 + 1) * W;
    const float* rb = img + yb * W;

    const int cl = (cb == 0)        ? 0       : cb - 1;  // left edge col
    const int cr = (cb == W - 4)    ? W - 1   : cb + 4;  // right edge col

    // ---- issue all 12 loads up-front (unconditional, clamped) ----
    const float4 vt = *reinterpret_cast<const float4*>(rt  + cb);
    const float4 v1 = *reinterpret_cast<const float4*>(r1p + cb);
    const float4 v2 = *reinterpret_cast<const float4*>(r2p + cb);
    const float4 vb = *reinterpret_cast<const float4*>(rb  + cb);
    const float lt = __ldg(rt + cl),  rt_ = __ldg(rt + cr);
    const float l1 = __ldg(r1p + cl), r1_ = __ldg(r1p + cr);
    const float l2 = __ldg(r2p + cl), r2_ = __ldg(r2p + cr);
    const float lb = __ldg(rb + cl),  rb_ = __ldg(rb + cr);

    // ---- masks (applied via FMUL on the fma pipe) ----
    const float mt = (y0 > 0)      ? 1.0f : 0.0f;   // top row valid
    const float mb = (y0 < H - 2)  ? 1.0f : 0.0f;   // bottom row valid
    const float ml = (cb > 0)      ? 1.0f : 0.0f;   // left col valid
    const float mr = (cb < W - 4)  ? 1.0f : 0.0f;   // right col valid

    float c0[6], c1[6], c2[6], c3[6];
    c0[0] = lt * (mt * ml); c0[1] = vt.x * mt; c0[2] = vt.y * mt;
    c0[3] = vt.z * mt;      c0[4] = vt.w * mt; c0[5] = rt_ * (mt * mr);
    c1[0] = l1 * ml; c1[1] = v1.x; c1[2] = v1.y;
    c1[3] = v1.z;    c1[4] = v1.w; c1[5] = r1_ * mr;
    c2[0] = l2 * ml; c2[1] = v2.x; c2[2] = v2.y;
    c2[3] = v2.z;    c2[4] = v2.w; c2[5] = r2_ * mr;
    c3[0] = lb * (mb * ml); c3[1] = vb.x * mb; c3[2] = vb.y * mb;
    c3[3] = vb.z * mb;      c3[4] = vb.w * mb; c3[5] = rb_ * (mb * mr);

    // ---- shared sort2 of the two middle rows, per column ----
    float mn[6], mx[6];
    #pragma unroll
    for (int i = 0; i < 6; i++) {
        mn[i] = fminf(c1[i], c2[i]);
        mx[i] = fmaxf(c1[i], c2[i]);
    }

    float lo[6], mi[6], hi[6], o[4];

    // Output row y0: triple (top, mn, mx)
    #pragma unroll
    for (int i = 0; i < 6; i++) {
        const float a = c0[i];
        lo[i] = fminf(a, mn[i]);
        hi[i] = fmaxf(a, mx[i]);
        mi[i] = fmaxf(mn[i], fminf(a, mx[i]));
    }
    combine_row(lo, mi, hi, o);
    {
        float4 res; res.x = o[0]; res.y = o[1]; res.z = o[2]; res.w = o[3];
        *reinterpret_cast<float4*>(out + ((size_t)rp * 2 * W) + cb) = res;
    }

    // Output row y0+1: triple (mn, mx, bottom)
    #pragma unroll
    for (int i = 0; i < 6; i++) {
        const float d = c3[i];
        lo[i] = fminf(d, mn[i]);
        hi[i] = fmaxf(d, mx[i]);
        mi[i] = fmaxf(mn[i], fminf(d, mx[i]));
    }
    combine_row(lo, mi, hi, o);
    {
        float4 res; res.x = o[0]; res.y = o[1]; res.z = o[2]; res.w = o[3];
        *reinterpret_cast<float4*>(out + ((size_t)(rp * 2 + 1) * W) + cb) = res;
    }
}

extern "C" void kernel_launch(void* const* d_in, const int* in_sizes, int n_in,
                              void* d_out, int out_size) {
    const float* x = (const float*)d_in[0];
    float* out = (float*)d_out;

    const int total_threads = (NIMG * H * W) / 8;   // 3,145,728
    const int block = 256;
    const int grid = total_threads / block;          // 12288
    median3x3_kernel<<<grid, block>>>(x, out);
}

// round 5
// speedup vs baseline: 1.2892x; 1.0839x over previous
#include <cuda_runtime.h>
#include <cuda_bf16.h>

// 3x3 median filter, zero padding, exact median of 9.
// x: (32, 3, 512, 512) fp32 -> 96 images of 512x512.
//
// Thread = 4 columns x 4 output rows (16 px). Loads 6 input rows once
// (unconditional, clamped addresses; zero-padding via exact 0/1 FMUL masks
// on the fma pipe). Lanes contiguous in x (16B stride) -> minimal L1
// wavefronts. Each row-pair shares sort2 of its two middle rows.
// Exact min/max network only: ~17.5 FMNMX/pixel, 1.125 loads/pixel.

#define W 512
#define H 512
#define NIMG 96

__device__ __forceinline__ float med3(float a, float b, float c) {
    return fmaxf(fminf(a, b), fminf(fmaxf(a, b), c));
}

// Combine one output row from sorted column triples lo/mi/hi[6] -> o[4].
__device__ __forceinline__ void combine_row(const float* lo, const float* mi,
                                            const float* hi, float* o) {
    float wl[4], wh[4], wm[4];
    #pragma unroll
    for (int t = 0; t < 2; t++) {
        const int i = 2 * t + 1;
        const float A = fmaxf(lo[i], lo[i + 1]);
        wl[2 * t]     = fmaxf(A, lo[2 * t]);
        wl[2 * t + 1] = fmaxf(A, lo[2 * t + 3]);
        const float B = fminf(hi[i], hi[i + 1]);
        wh[2 * t]     = fminf(B, hi[2 * t]);
        wh[2 * t + 1] = fminf(B, hi[2 * t + 3]);
        const float mn = fminf(mi[i], mi[i + 1]);
        const float mx = fmaxf(mi[i], mi[i + 1]);
        wm[2 * t]     = fmaxf(mn, fminf(mx, mi[2 * t]));
        wm[2 * t + 1] = fminf(mx, fmaxf(mn, mi[2 * t + 3]));
    }
    #pragma unroll
    for (int j = 0; j < 4; j++)
        o[j] = med3(wl[j], wm[j], wh[j]);
}

__global__ void __launch_bounds__(256, 4)
median3x3_kernel(const float* __restrict__ x, float* __restrict__ out) {
    const int tid = blockIdx.x * blockDim.x + threadIdx.x;
    const int cb  = (tid & 127) << 2;          // column base (0..508)
    const int sid = tid >> 7;                  // strip id
    const int y0  = (sid & 127) << 2;          // strip top row (0..508, step 4)
    const size_t ibase = (size_t)(sid >> 7) * (H * W);
    const float* img = x + ibase;
    float* oimg = out + ibase;

    const int cl = (cb == 0)     ? 0     : cb - 1;
    const int cr = (cb == W - 4) ? W - 1 : cb + 4;
    const float ml = (cb > 0)     ? 1.0f : 0.0f;
    const float mr = (cb < W - 4) ? 1.0f : 0.0f;

    // Load 6 rows (y0-1 .. y0+4), 6 columns each, unconditional + masked.
    float c[6][6];
    #pragma unroll
    for (int i = 0; i < 6; i++) {
        int yy = y0 - 1 + i;
        const float mrow = (yy >= 0 && yy < H) ? 1.0f : 0.0f;
        yy = min(max(yy, 0), H - 1);
        const float* rowp = img + yy * W;
        const float4 v = *reinterpret_cast<const float4*>(rowp + cb);
        const float l = __ldg(rowp + cl);
        const float r = __ldg(rowp + cr);
        c[i][0] = l * (ml * mrow);
        c[i][1] = v.x * mrow; c[i][2] = v.y * mrow;
        c[i][3] = v.z * mrow; c[i][4] = v.w * mrow;
        c[i][5] = r * (mr * mrow);
    }

    // Two row-pairs: pair p uses rows (2p, 2p+1, 2p+2, 2p+3).
    #pragma unroll
    for (int p = 0; p < 2; p++) {
        const float* top = c[2 * p];
        const float* m1  = c[2 * p + 1];
        const float* m2  = c[2 * p + 2];
        const float* bot = c[2 * p + 3];

        float mn[6], mx[6];
        #pragma unroll
        for (int i = 0; i < 6; i++) {
            mn[i] = fminf(m1[i], m2[i]);
            mx[i] = fmaxf(m1[i], m2[i]);
        }

        float lo[6], mi[6], hi[6], o[4];

        // Output row y0 + 2p: triple (top, mn, mx)
        #pragma unroll
        for (int i = 0; i < 6; i++) {
            const float a = top[i];
            lo[i] = fminf(a, mn[i]);
            hi[i] = fmaxf(a, mx[i]);
            mi[i] = fmaxf(mn[i], fminf(a, mx[i]));
        }
        combine_row(lo, mi, hi, o);
        {
            float4 res; res.x = o[0]; res.y = o[1]; res.z = o[2]; res.w = o[3];
            *reinterpret_cast<float4*>(oimg + (size_t)(y0 + 2 * p) * W + cb) = res;
        }

        // Output row y0 + 2p + 1: triple (mn, mx, bot)
        #pragma unroll
        for (int i = 0; i < 6; i++) {
            const float d = bot[i];
            lo[i] = fminf(d, mn[i]);
            hi[i] = fmaxf(d, mx[i]);
            mi[i] = fmaxf(mn[i], fminf(d, mx[i]));
        }
        combine_row(lo, mi, hi, o);
        {
            float4 res; res.x = o[0]; res.y = o[1]; res.z = o[2]; res.w = o[3];
            *reinterpret_cast<float4*>(oimg + (size_t)(y0 + 2 * p + 1) * W + cb) = res;
        }
    }
}

extern "C" void kernel_launch(void* const* d_in, const int* in_sizes, int n_in,
                              void* d_out, int out_size) {
    const float* x = (const float*)d_in[0];
    float* out = (float*)d_out;

    const int total_threads = (NIMG * H * W) / 16;   // 1,572,864
    const int block = 256;
    const int grid = total_threads / block;           // 6144
    median3x3_kernel<<<grid, block>>>(x, out);
}

// round 6
// speedup vs baseline: 1.4118x; 1.0951x over previous
#include <cuda_runtime.h>
#include <cuda_bf16.h>

// 3x3 median filter, zero padding, exact median of 9.
// x: (32, 3, 512, 512) fp32 -> 96 images of 512x512.
//
// Thread = 4 columns x 4 output rows (16 px). Restructured for register
// pressure: rows are loaded/consumed in liveness order so at most ~4 row
// buffers are live at once; __launch_bounds__(256,5) caps regs at 51 to get
// 40 warps/SM. Row masks only where a row can be out of bounds. Exact
// min/max network (~16.5 FMNMX/px); zero-padding via exact 0/1 FMUL masks.

#define W 512
#define H 512
#define NIMG 96

__device__ __forceinline__ float med3(float a, float b, float c) {
    return fmaxf(fminf(a, b), fminf(fmaxf(a, b), c));
}

// Load one row's 6-column window (cb-1 .. cb+4), clamped addresses.
// MASK_ROW: multiply by mrow (0/1) for vertically out-of-bounds rows.
template <bool MASK_ROW>
__device__ __forceinline__ void load_row(const float* __restrict__ rowp,
                                         int cb, int cl, int cr,
                                         float ml, float mr, float mrow,
                                         float* c) {
    const float4 v = *reinterpret_cast<const float4*>(rowp + cb);
    const float l = __ldg(rowp + cl);
    const float r = __ldg(rowp + cr);
    if (MASK_ROW) {
        c[0] = l * (ml * mrow);
        c[1] = v.x * mrow; c[2] = v.y * mrow;
        c[3] = v.z * mrow; c[4] = v.w * mrow;
        c[5] = r * (mr * mrow);
    } else {
        c[0] = l * ml;
        c[1] = v.x; c[2] = v.y; c[3] = v.z; c[4] = v.w;
        c[5] = r * mr;
    }
}

// Emit one output row: insert row a into the shared sort2 (mn, mx) of the
// other two rows, combine 3-wide windows with pair sharing, store float4.
__device__ __forceinline__ void emit_row(const float* a, const float* mn,
                                         const float* mx,
                                         float* __restrict__ outp) {
    float lo[6], mi[6], hi[6];
    #pragma unroll
    for (int i = 0; i < 6; i++) {
        lo[i] = fminf(a[i], mn[i]);
        hi[i] = fmaxf(a[i], mx[i]);
        mi[i] = fmaxf(mn[i], fminf(a[i], mx[i]));
    }
    float o[4];
    #pragma unroll
    for (int t = 0; t < 2; t++) {
        const int i = 2 * t + 1;
        const float A = fmaxf(lo[i], lo[i + 1]);
        const float B = fminf(hi[i], hi[i + 1]);
        const float n = fminf(mi[i], mi[i + 1]);
        const float m = fmaxf(mi[i], mi[i + 1]);
        const float wl0 = fmaxf(A, lo[2 * t]);
        const float wl1 = fmaxf(A, lo[2 * t + 3]);
        const float wh0 = fminf(B, hi[2 * t]);
        const float wh1 = fminf(B, hi[2 * t + 3]);
        const float wm0 = fmaxf(n, fminf(m, mi[2 * t]));
        const float wm1 = fminf(m, fmaxf(n, mi[2 * t + 3]));
        o[2 * t]     = med3(wl0, wm0, wh0);
        o[2 * t + 1] = med3(wl1, wm1, wh1);
    }
    float4 res; res.x = o[0]; res.y = o[1]; res.z = o[2]; res.w = o[3];
    *reinterpret_cast<float4*>(outp) = res;
}

__global__ void __launch_bounds__(256, 5)
median3x3_kernel(const float* __restrict__ x, float* __restrict__ out) {
    const int tid = blockIdx.x * blockDim.x + threadIdx.x;
    const int cb  = (tid & 127) << 2;          // column base (0..508)
    const int sid = tid >> 7;                  // strip id
    const int y0  = (sid & 127) << 2;          // strip top output row (step 4)
    const size_t ibase = (size_t)(sid >> 7) * (H * W);
    const float* img = x + ibase;
    float* oimg = out + ibase;

    const int cl = (cb == 0)     ? 0     : cb - 1;
    const int cr = (cb == W - 4) ? W - 1 : cb + 4;
    const float ml = (cb > 0)     ? 1.0f : 0.0f;
    const float mr = (cb < W - 4) ? 1.0f : 0.0f;

    // Rows y0..y0+3 are always in-bounds (y0 in [0,508]).
    const float mt = (y0 > 0)     ? 1.0f : 0.0f;   // row y0-1
    const float mb = (y0 < H - 4) ? 1.0f : 0.0f;   // row y0+4

    float ra[6], rb[6], rc[6], rd[6], re[6], rf[6];
    float mn[6], mx[6];

    // --- pair 0: output rows y0, y0+1 (inputs y0-1 .. y0+2) ---
    load_row<true >(img + (y0 > 0 ? y0 - 1 : 0) * W, cb, cl, cr, ml, mr, mt, ra);
    load_row<false>(img + (y0    ) * W, cb, cl, cr, ml, mr, 1.0f, rb);
    load_row<false>(img + (y0 + 1) * W, cb, cl, cr, ml, mr, 1.0f, rc);
    load_row<false>(img + (y0 + 2) * W, cb, cl, cr, ml, mr, 1.0f, rd);

    #pragma unroll
    for (int i = 0; i < 6; i++) {              // rb dead after this
        mn[i] = fminf(rb[i], rc[i]);
        mx[i] = fmaxf(rb[i], rc[i]);
    }
    emit_row(ra, mn, mx, oimg + (size_t)y0 * W + cb);        // ra dead
    emit_row(rd, mn, mx, oimg + (size_t)(y0 + 1) * W + cb);  // mn,mx dead

    // --- pair 1: output rows y0+2, y0+3 (inputs y0+1 .. y0+4) ---
    load_row<false>(img + (y0 + 3) * W, cb, cl, cr, ml, mr, 1.0f, re);
    load_row<true >(img + (y0 + 4 < H ? y0 + 4 : H - 1) * W, cb, cl, cr, ml, mr, mb, rf);

    #pragma unroll
    for (int i = 0; i < 6; i++) {              // rd, re dead after this
        mn[i] = fminf(rd[i], re[i]);
        mx[i] = fmaxf(rd[i], re[i]);
    }
    emit_row(rc, mn, mx, oimg + (size_t)(y0 + 2) * W + cb);
    emit_row(rf, mn, mx, oimg + (size_t)(y0 + 3) * W + cb);
}

extern "C" void kernel_launch(void* const* d_in, const int* in_sizes, int n_in,
                              void* d_out, int out_size) {
    const float* x = (const float*)d_in[0];
    float* out = (float*)d_out;

    const int total_threads = (NIMG * H * W) / 16;   // 1,572,864
    const int block = 256;
    const int grid = total_threads / block;           // 6144
    median3x3_kernel<<<grid, block>>>(x, out);
}